// round 12
// baseline (speedup 1.0000x reference)
#include <cuda_runtime.h>
#include <math_constants.h>

#define N_NODES 100000
#define N_EDGES 1600000
#define D 64

// Scratch (allocation-free: __device__ globals)
__device__ float g_w[N_NODES];          // exp(h . Wk) per node
__device__ int   g_deg[N_NODES];        // in-degree histogram
__device__ int   g_off[N_NODES + 1];    // CSR offsets (exclusive scan)
__device__ int   g_cur[N_NODES];        // fill cursors
__device__ int   g_csr_src[N_EDGES];    // src node id, grouped by dst

// ---------------------------------------------------------------------------
// L0: warp per node — w = exp(h . Wk); zero degree histogram.
// Softmax identity: score = aq[dst]+ak[src]+b, and aq[dst]+b is constant per
// dst group, so it cancels exactly in e/sum(e). Only exp(ak[src]) matters.
// ---------------------------------------------------------------------------
__global__ void k_prep(const float* __restrict__ h,
                       const float* __restrict__ W) {
    int node = (blockIdx.x * blockDim.x + threadIdx.x) >> 5;
    int lane = threadIdx.x & 31;
    if (node >= N_NODES) return;
    const float* hr = h + (size_t)node * D;
    float ak = hr[lane] * W[D + lane] + hr[lane + 32] * W[D + lane + 32];
    #pragma unroll
    for (int off = 16; off > 0; off >>= 1)
        ak += __shfl_down_sync(0xffffffffu, ak, off);
    if (lane == 0) {
        g_w[node]   = expf(ak);
        g_deg[node] = 0;
    }
}

// ---------------------------------------------------------------------------
// L1: degree histogram over dst (4 edges per thread, vector loads)
// ---------------------------------------------------------------------------
__global__ void k_hist(const int* __restrict__ ei) {
    int t = blockIdx.x * blockDim.x + threadIdx.x;
    if (t >= N_EDGES / 4) return;
    int4 d4 = ((const int4*)(ei + N_EDGES))[t];
    atomicAdd(&g_deg[d4.x], 1);
    atomicAdd(&g_deg[d4.y], 1);
    atomicAdd(&g_deg[d4.z], 1);
    atomicAdd(&g_deg[d4.w], 1);
}

// ---------------------------------------------------------------------------
// L2: single-block exclusive scan of g_deg -> g_off, g_cur.
// 1024 threads, each owns a contiguous chunk of ceil(N/1024) nodes.
// ---------------------------------------------------------------------------
__global__ void k_scan() {
    const int T = 1024;
    const int C = (N_NODES + T - 1) / T;   // 98
    __shared__ int warp_sums[32];
    __shared__ int warp_pref[33];
    int tid  = threadIdx.x;
    int lane = tid & 31, wid = tid >> 5;
    int beg = tid * C;
    int end = min(beg + C, N_NODES);
    int local = 0;
    for (int i = beg; i < end; i++) local += g_deg[i];
    // inclusive warp scan of per-thread sums
    int v = local;
    #pragma unroll
    for (int off = 1; off < 32; off <<= 1) {
        int n = __shfl_up_sync(0xffffffffu, v, off);
        if (lane >= off) v += n;
    }
    if (lane == 31) warp_sums[wid] = v;
    __syncthreads();
    if (wid == 0) {
        int s = warp_sums[lane];
        #pragma unroll
        for (int off = 1; off < 32; off <<= 1) {
            int n = __shfl_up_sync(0xffffffffu, s, off);
            if (lane >= off) s += n;
        }
        warp_pref[lane + 1] = s;
        if (lane == 0) warp_pref[0] = 0;
    }
    __syncthreads();
    int run = warp_pref[wid] + (v - local);  // exclusive prefix for this thread
    for (int i = beg; i < end; i++) {
        int d = g_deg[i];
        g_off[i] = run;
        g_cur[i] = run;
        run += d;
    }
    if (tid == T - 1) g_off[N_NODES] = run;  // == N_EDGES
}

// ---------------------------------------------------------------------------
// L3: CSR fill — slot = cursor[dst]++, store src (4 edges per thread)
// ---------------------------------------------------------------------------
__global__ void k_fill(const int* __restrict__ ei) {
    int t = blockIdx.x * blockDim.x + threadIdx.x;
    if (t >= N_EDGES / 4) return;
    int4 s4 = ((const int4*)ei)[t];
    int4 d4 = ((const int4*)(ei + N_EDGES))[t];
    int src[4] = {s4.x, s4.y, s4.z, s4.w};
    int dst[4] = {d4.x, d4.y, d4.z, d4.w};
    #pragma unroll
    for (int i = 0; i < 4; i++) {
        int slot = atomicAdd(&g_cur[dst[i]], 1);
        g_csr_src[slot] = src[i];
    }
}

// ---------------------------------------------------------------------------
// L4: aggregation — 2 warps per node (32 dims each). Walk the node's edge
// list, accumulate sum(w) and sum(w * h[src]) in registers, ONE store per
// node half. No output atomics at all (was 410MB of RED traffic).
// Unroll x4 keeps 4 independent h-gathers in flight.
// ---------------------------------------------------------------------------
__global__ void k_agg(const float* __restrict__ h,
                      float* __restrict__ out) {
    int gw   = (blockIdx.x * blockDim.x + threadIdx.x) >> 5;
    int lane = threadIdx.x & 31;
    int node = gw >> 1;
    if (node >= N_NODES) return;
    int dimo = (gw & 1) * 32 + lane;

    int beg = g_off[node];
    int end = g_off[node + 1];

    float acc = 0.0f, sum = 0.0f;
    int i = beg;
    for (; i + 4 <= end; i += 4) {
        int s0 = g_csr_src[i];
        int s1 = g_csr_src[i + 1];
        int s2 = g_csr_src[i + 2];
        int s3 = g_csr_src[i + 3];
        float w0 = __ldg(g_w + s0), w1 = __ldg(g_w + s1);
        float w2 = __ldg(g_w + s2), w3 = __ldg(g_w + s3);
        float h0 = __ldg(h + (size_t)s0 * D + dimo);
        float h1 = __ldg(h + (size_t)s1 * D + dimo);
        float h2 = __ldg(h + (size_t)s2 * D + dimo);
        float h3 = __ldg(h + (size_t)s3 * D + dimo);
        sum += (w0 + w1) + (w2 + w3);
        acc += w0 * h0 + w1 * h1 + w2 * h2 + w3 * h3;
    }
    for (; i < end; i++) {
        int s = g_csr_src[i];
        float w = __ldg(g_w + s);
        acc += w * __ldg(h + (size_t)s * D + dimo);
        sum += w;
    }
    out[(size_t)node * D + dimo] = acc / (sum + 1e-16f);
}

// ---------------------------------------------------------------------------
extern "C" void kernel_launch(void* const* d_in, const int* in_sizes, int n_in,
                              void* d_out, int out_size) {
    const float* h   = (const float*)d_in[0];
    const float* W   = (const float*)d_in[2];
    const int*   ei  = (const int*)d_in[4];
    float*       out = (float*)d_out;

    // L0: node weights + zero histogram (warp per node, 8 warps/block)
    k_prep<<<(N_NODES + 7) / 8, 256>>>(h, W);
    // L1: degree histogram (4 edges/thread)
    k_hist<<<(N_EDGES / 4 + 255) / 256, 256>>>(ei);
    // L2: exclusive scan (single block)
    k_scan<<<1, 1024>>>();
    // L3: CSR fill
    k_fill<<<(N_EDGES / 4 + 255) / 256, 256>>>(ei);
    // L4: gather-side aggregation — 2 warps/node, 8 warps/block
    k_agg<<<(N_NODES * 2 + 7) / 8, 256>>>(h, out);
}

// round 13
// speedup vs baseline: 2.3071x; 2.3071x over previous
#include <cuda_runtime.h>
#include <math_constants.h>

#define N_NODES 100000
#define N_EDGES 1600000
#define D 64

// Scratch (allocation-free: __device__ globals)
__device__ float g_w[N_NODES];        // exp(h . Wk) per node
__device__ float g_rinv[N_NODES];     // seg_sum, then 1/(seg_sum+eps)

// ---------------------------------------------------------------------------
// L0: warp per node. Softmax identity: score = aq[dst]+ak[src]+b and
// aq[dst]+b is constant within a dst group, so it cancels exactly in the
// softmax. Per-edge weight = w[src]/sum(w), w = exp(h . Wk). So only the
// k-projection of h is needed; hq/Wq/bias drop out entirely.
// Also inits seg_sum accumulator and zeroes the output row.
// ---------------------------------------------------------------------------
__global__ void k_prep(const float* __restrict__ h,
                       const float* __restrict__ W,
                       float* __restrict__ out) {
    int node = (blockIdx.x * blockDim.x + threadIdx.x) >> 5;
    int lane = threadIdx.x & 31;
    if (node >= N_NODES) return;
    const float* hr = h + (size_t)node * D;
    float ak = hr[lane] * W[D + lane] + hr[lane + 32] * W[D + lane + 32];
    #pragma unroll
    for (int off = 16; off > 0; off >>= 1)
        ak += __shfl_down_sync(0xffffffffu, ak, off);
    if (lane == 0) {
        g_w[node]    = expf(ak);
        g_rinv[node] = 0.0f;          // accumulator for sum(w)
    }
    out[(size_t)node * D + lane]      = 0.0f;
    out[(size_t)node * D + lane + 32] = 0.0f;
}

// ---------------------------------------------------------------------------
// L1: per-edge segment sum of w[src] into dst groups. 4 edges/thread,
// vector index loads, 4 independent w-gathers in flight, 4 scattered REDs.
// ---------------------------------------------------------------------------
__global__ void k_sum(const int* __restrict__ ei) {
    int t = blockIdx.x * blockDim.x + threadIdx.x;
    if (t >= N_EDGES / 4) return;
    int4 s4 = ((const int4*)ei)[t];
    int4 d4 = ((const int4*)(ei + N_EDGES))[t];
    float w0 = __ldg(g_w + s4.x);
    float w1 = __ldg(g_w + s4.y);
    float w2 = __ldg(g_w + s4.z);
    float w3 = __ldg(g_w + s4.w);
    atomicAdd(&g_rinv[d4.x], w0);
    atomicAdd(&g_rinv[d4.y], w1);
    atomicAdd(&g_rinv[d4.z], w2);
    atomicAdd(&g_rinv[d4.w], w3);
}

// ---------------------------------------------------------------------------
// L2: per-node reciprocal (removes the divide + eps-add from the edge loop)
// ---------------------------------------------------------------------------
__global__ void k_rinv() {
    int n = blockIdx.x * blockDim.x + threadIdx.x;
    if (n >= N_NODES) return;
    g_rinv[n] = 1.0f / (g_rinv[n] + 1e-16f);
}

// ---------------------------------------------------------------------------
// L3: scatter. Warp = 32 dims (one half-row) x 8 edges. Metadata arrives via
// aligned vector loads (warp-uniform broadcasts); 8 w-gathers + 8 rinv
// gathers + 8 h-gathers issue independently (MLP ~8). Per edge the 32
// lanes' atomicAdds form one coalesced 128B RED wavefront.
// ---------------------------------------------------------------------------
__global__ void k_scatter(const int* __restrict__ ei,
                          const float* __restrict__ h,
                          float* __restrict__ out) {
    int gw   = (blockIdx.x * blockDim.x + threadIdx.x) >> 5;  // global warp id
    int lane = threadIdx.x & 31;
    int half = gw & 1;                 // which 32-dim half of D=64
    int e0   = (gw >> 1) << 3;         // 8 consecutive edges per warp-pair
    int dimo = half * 32 + lane;

    int4 sa = ((const int4*)(ei + e0))[0];
    int4 sb = ((const int4*)(ei + e0))[1];
    int4 da = ((const int4*)(ei + N_EDGES + e0))[0];
    int4 db = ((const int4*)(ei + N_EDGES + e0))[1];
    int src[8] = {sa.x, sa.y, sa.z, sa.w, sb.x, sb.y, sb.z, sb.w};
    int dst[8] = {da.x, da.y, da.z, da.w, db.x, db.y, db.z, db.w};

    float w[8], ri[8];
    #pragma unroll
    for (int i = 0; i < 8; i++) w[i] = __ldg(g_w + src[i]);
    #pragma unroll
    for (int i = 0; i < 8; i++) ri[i] = __ldg(g_rinv + dst[i]);
    float hv[8];
    #pragma unroll
    for (int i = 0; i < 8; i++) hv[i] = __ldg(h + (size_t)src[i] * D + dimo);
    #pragma unroll
    for (int i = 0; i < 8; i++) {
        float a = w[i] * ri[i];
        atomicAdd(out + (size_t)dst[i] * D + dimo, hv[i] * a);
    }
}

// ---------------------------------------------------------------------------
extern "C" void kernel_launch(void* const* d_in, const int* in_sizes, int n_in,
                              void* d_out, int out_size) {
    const float* h   = (const float*)d_in[0];
    const float* W   = (const float*)d_in[2];
    const int*   ei  = (const int*)d_in[4];
    float*       out = (float*)d_out;

    // L0: node weights + zero out + init sums (warp/node, 8 warps/block)
    k_prep<<<(N_NODES + 7) / 8, 256>>>(h, W, out);
    // L1: segment sum of w over dst (4 edges/thread)
    k_sum<<<(N_EDGES / 4 + 255) / 256, 256>>>(ei);
    // L2: per-node reciprocal
    k_rinv<<<(N_NODES + 255) / 256, 256>>>();
    // L3: scatter — warp-pair covers 8 edges x 64 dims.
    // warps = (E/8)*2 = 400000, blocks of 8 warps = 50000 exactly.
    {
        int warps  = (N_EDGES / 8) * 2;
        int blocks = warps / 8;
        k_scatter<<<blocks, 256>>>(ei, h, out);
    }
}

// round 14
// speedup vs baseline: 2.5436x; 1.1025x over previous
#include <cuda_runtime.h>
#include <cuda_fp16.h>
#include <math_constants.h>

#define N_NODES 100000
#define N_EDGES 1600000
#define D 64

// Scratch (allocation-free: __device__ globals)
__device__ float  g_w[N_NODES];            // exp(h . Wk) per node
__device__ float  g_rinv[N_NODES];         // seg_sum, then 1/(seg_sum+eps)
__device__ __half g_hw[(size_t)N_NODES * D]; // fp16(w * h), per node row

// ---------------------------------------------------------------------------
// L0: warp per node. Softmax identity: score = aq[dst]+ak[src]+b and
// aq[dst]+b is constant within a dst group -> cancels exactly in softmax.
// Per-edge weight = w[src]/sum_dst(w), w = exp(h . Wk).
// Pre-multiplies w into h as fp16 (halves scatter gather bytes; REDs stay
// fp32 so accumulation precision is unchanged). Also zeroes out + sums.
// ---------------------------------------------------------------------------
__global__ void k_prep(const float* __restrict__ h,
                       const float* __restrict__ W,
                       float* __restrict__ out) {
    int node = (blockIdx.x * blockDim.x + threadIdx.x) >> 5;
    int lane = threadIdx.x & 31;
    if (node >= N_NODES) return;
    const float* hr = h + (size_t)node * D;
    float h0 = hr[lane], h1 = hr[lane + 32];
    float ak = h0 * W[D + lane] + h1 * W[D + lane + 32];
    #pragma unroll
    for (int off = 16; off > 0; off >>= 1)          // xor-reduce: all lanes get sum
        ak += __shfl_xor_sync(0xffffffffu, ak, off);
    float w = expf(ak);
    if (lane == 0) {
        g_w[node]    = w;
        g_rinv[node] = 0.0f;          // accumulator for sum(w)
    }
    g_hw[(size_t)node * D + lane]      = __float2half(w * h0);
    g_hw[(size_t)node * D + lane + 32] = __float2half(w * h1);
    out[(size_t)node * D + lane]      = 0.0f;
    out[(size_t)node * D + lane + 32] = 0.0f;
}

// ---------------------------------------------------------------------------
// L1: per-edge segment sum of w[src] into dst groups. 4 edges/thread.
// ---------------------------------------------------------------------------
__global__ void k_sum(const int* __restrict__ ei) {
    int t = blockIdx.x * blockDim.x + threadIdx.x;
    if (t >= N_EDGES / 4) return;
    int4 s4 = ((const int4*)ei)[t];
    int4 d4 = ((const int4*)(ei + N_EDGES))[t];
    float w0 = __ldg(g_w + s4.x);
    float w1 = __ldg(g_w + s4.y);
    float w2 = __ldg(g_w + s4.z);
    float w3 = __ldg(g_w + s4.w);
    atomicAdd(&g_rinv[d4.x], w0);
    atomicAdd(&g_rinv[d4.y], w1);
    atomicAdd(&g_rinv[d4.z], w2);
    atomicAdd(&g_rinv[d4.w], w3);
}

// ---------------------------------------------------------------------------
// L2: per-node reciprocal
// ---------------------------------------------------------------------------
__global__ void k_rinv() {
    int n = blockIdx.x * blockDim.x + threadIdx.x;
    if (n >= N_NODES) return;
    g_rinv[n] = 1.0f / (g_rinv[n] + 1e-16f);
}

// ---------------------------------------------------------------------------
// L3: scatter (unnormalized). ONE warp = 8 edges x all 64 dims; lane covers
// dims (lane, lane+32). Per 8 edges: 4 index-vector broadcasts + 16 fp16
// 64B gathers + 16 coalesced fp32 RED wavefronts — no w/rinv loads at all
// (w folded into g_hw; normalization deferred to k_norm).
// ---------------------------------------------------------------------------
__global__ void k_scatter(const int* __restrict__ ei,
                          float* __restrict__ out) {
    int gw   = (blockIdx.x * blockDim.x + threadIdx.x) >> 5;  // warp id
    int lane = threadIdx.x & 31;
    int e0   = gw << 3;                // 8 consecutive edges per warp
    if (e0 >= N_EDGES) return;

    int4 sa = ((const int4*)(ei + e0))[0];
    int4 sb = ((const int4*)(ei + e0))[1];
    int4 da = ((const int4*)(ei + N_EDGES + e0))[0];
    int4 db = ((const int4*)(ei + N_EDGES + e0))[1];
    int src[8] = {sa.x, sa.y, sa.z, sa.w, sb.x, sb.y, sb.z, sb.w};
    int dst[8] = {da.x, da.y, da.z, da.w, db.x, db.y, db.z, db.w};

    __half v0[8], v1[8];
    #pragma unroll
    for (int i = 0; i < 8; i++) v0[i] = __ldg(g_hw + (size_t)src[i] * D + lane);
    #pragma unroll
    for (int i = 0; i < 8; i++) v1[i] = __ldg(g_hw + (size_t)src[i] * D + lane + 32);
    #pragma unroll
    for (int i = 0; i < 8; i++) {
        float* p = out + (size_t)dst[i] * D + lane;
        atomicAdd(p,      __half2float(v0[i]));
        atomicAdd(p + 32, __half2float(v1[i]));
    }
}

// ---------------------------------------------------------------------------
// L4: normalize — out[n] *= rinv[n], float4 vectorized (L2-resident).
// ---------------------------------------------------------------------------
__global__ void k_norm(float* __restrict__ out) {
    int t = blockIdx.x * blockDim.x + threadIdx.x;
    if (t >= N_NODES * D / 4) return;
    int node = t >> 4;                 // 16 float4 per node row
    float ri = __ldg(g_rinv + node);
    float4 v = ((float4*)out)[t];
    v.x *= ri; v.y *= ri; v.z *= ri; v.w *= ri;
    ((float4*)out)[t] = v;
}

// ---------------------------------------------------------------------------
extern "C" void kernel_launch(void* const* d_in, const int* in_sizes, int n_in,
                              void* d_out, int out_size) {
    const float* h   = (const float*)d_in[0];
    const float* W   = (const float*)d_in[2];
    const int*   ei  = (const int*)d_in[4];
    float*       out = (float*)d_out;

    // L0: node weights + hw=fp16(w*h) + zero out/sums (warp/node)
    k_prep<<<(N_NODES + 7) / 8, 256>>>(h, W, out);
    // L1: segment sum of w over dst (4 edges/thread)
    k_sum<<<(N_EDGES / 4 + 255) / 256, 256>>>(ei);
    // L2: per-node reciprocal
    k_rinv<<<(N_NODES + 255) / 256, 256>>>();
    // L3: scatter — warp covers 8 edges x 64 dims; warps = E/8 = 200000.
    {
        int warps  = N_EDGES / 8;
        int blocks = warps / 8;        // 8 warps (256 threads) per block
        k_scatter<<<blocks, 256>>>(ei, out);
    }
    // L4: normalize rows by 1/sum(w)
    k_norm<<<(N_NODES * D / 4 + 255) / 256, 256>>>(out);
}

// round 15
// speedup vs baseline: 2.5922x; 1.0191x over previous
#include <cuda_runtime.h>
#include <cuda_fp16.h>
#include <math_constants.h>

#define N_NODES 100000
#define N_EDGES 1600000
#define D 64

// Scratch (allocation-free: __device__ globals)
__device__ float  g_w[N_NODES];              // exp(h . Wk) per node
__device__ float  g_sum[N_NODES];            // seg_sum of w over dst
__device__ __half g_hw[(size_t)N_NODES * D]; // fp16(w*h), INTERLEAVED layout:
                                             // row pos 2k   = dim k
                                             // row pos 2k+1 = dim k+32

// ---------------------------------------------------------------------------
// L0: warp per node. Softmax identity: score = aq[dst]+ak[src]+b and
// aq[dst]+b is constant within a dst group -> cancels exactly in softmax.
// Per-edge weight = w[src]/sum_dst(w), w = exp(h . Wk).
// Stores fp16(w*h) in an interleaved half2 layout so the scatter can fetch
// dims (lane, lane+32) with ONE half2 gather (one 128B wavefront per edge).
// ---------------------------------------------------------------------------
__global__ void k_prep(const float* __restrict__ h,
                       const float* __restrict__ W,
                       float* __restrict__ out) {
    int node = (blockIdx.x * blockDim.x + threadIdx.x) >> 5;
    int lane = threadIdx.x & 31;
    if (node >= N_NODES) return;
    const float* hr = h + (size_t)node * D;
    float h0 = hr[lane], h1 = hr[lane + 32];
    float ak = h0 * W[D + lane] + h1 * W[D + lane + 32];
    #pragma unroll
    for (int off = 16; off > 0; off >>= 1)          // xor-reduce: all lanes get sum
        ak += __shfl_xor_sync(0xffffffffu, ak, off);
    float w = expf(ak);
    if (lane == 0) {
        g_w[node]   = w;
        g_sum[node] = 0.0f;
    }
    ((__half2*)(g_hw + (size_t)node * D))[lane] = __floats2half2_rn(w * h0, w * h1);
    out[(size_t)node * D + lane]      = 0.0f;
    out[(size_t)node * D + lane + 32] = 0.0f;
}

// ---------------------------------------------------------------------------
// L1: per-edge segment sum of w[src] into dst groups. 4 edges/thread.
// ---------------------------------------------------------------------------
__global__ void k_sum(const int* __restrict__ ei) {
    int t = blockIdx.x * blockDim.x + threadIdx.x;
    if (t >= N_EDGES / 4) return;
    int4 s4 = ((const int4*)ei)[t];
    int4 d4 = ((const int4*)(ei + N_EDGES))[t];
    float w0 = __ldg(g_w + s4.x);
    float w1 = __ldg(g_w + s4.y);
    float w2 = __ldg(g_w + s4.z);
    float w3 = __ldg(g_w + s4.w);
    atomicAdd(&g_sum[d4.x], w0);
    atomicAdd(&g_sum[d4.y], w1);
    atomicAdd(&g_sum[d4.z], w2);
    atomicAdd(&g_sum[d4.w], w3);
}

// ---------------------------------------------------------------------------
// L2: scatter (unnormalized). ONE warp = 8 edges x all 64 dims; lane covers
// dims (lane, lane+32) via a single half2 gather per edge (interleaved
// g_hw layout). Per 8 edges: 4 index-vector broadcasts + 8 x 128B gather
// wavefronts + 16 x 128B coalesced fp32 RED wavefronts (was 36, now 28).
// ---------------------------------------------------------------------------
__global__ void k_scatter(const int* __restrict__ ei,
                          float* __restrict__ out) {
    int gw   = (blockIdx.x * blockDim.x + threadIdx.x) >> 5;  // warp id
    int lane = threadIdx.x & 31;
    int e0   = gw << 3;                // 8 consecutive edges per warp
    if (e0 >= N_EDGES) return;

    int4 sa = ((const int4*)(ei + e0))[0];
    int4 sb = ((const int4*)(ei + e0))[1];
    int4 da = ((const int4*)(ei + N_EDGES + e0))[0];
    int4 db = ((const int4*)(ei + N_EDGES + e0))[1];
    int src[8] = {sa.x, sa.y, sa.z, sa.w, sb.x, sb.y, sb.z, sb.w};
    int dst[8] = {da.x, da.y, da.z, da.w, db.x, db.y, db.z, db.w};

    __half2 v[8];
    #pragma unroll
    for (int i = 0; i < 8; i++)
        v[i] = __ldg((const __half2*)(g_hw + (size_t)src[i] * D) + lane);
    #pragma unroll
    for (int i = 0; i < 8; i++) {
        float2 f = __half22float2(v[i]);       // f.x = dim lane, f.y = dim lane+32
        float* p = out + (size_t)dst[i] * D + lane;
        atomicAdd(p,      f.x);
        atomicAdd(p + 32, f.y);
    }
}

// ---------------------------------------------------------------------------
// L3: normalize — out[n] *= 1/(sum[n]+eps), float4 vectorized (L2-resident).
// ---------------------------------------------------------------------------
__global__ void k_norm(float* __restrict__ out) {
    int t = blockIdx.x * blockDim.x + threadIdx.x;
    if (t >= N_NODES * D / 4) return;
    int node = t >> 4;                 // 16 float4 per node row
    float ri = 1.0f / (__ldg(g_sum + node) + 1e-16f);
    float4 v = ((float4*)out)[t];
    v.x *= ri; v.y *= ri; v.z *= ri; v.w *= ri;
    ((float4*)out)[t] = v;
}

// ---------------------------------------------------------------------------
extern "C" void kernel_launch(void* const* d_in, const int* in_sizes, int n_in,
                              void* d_out, int out_size) {
    const float* h   = (const float*)d_in[0];
    const float* W   = (const float*)d_in[2];
    const int*   ei  = (const int*)d_in[4];
    float*       out = (float*)d_out;

    // L0: node weights + interleaved hw=fp16(w*h) + zero out/sums
    k_prep<<<(N_NODES + 7) / 8, 256>>>(h, W, out);
    // L1: segment sum of w over dst (4 edges/thread)
    k_sum<<<(N_EDGES / 4 + 255) / 256, 256>>>(ei);
    // L2: scatter — warp covers 8 edges x 64 dims; warps = E/8 = 200000.
    {
        int warps  = N_EDGES / 8;
        int blocks = warps / 8;        // 8 warps (256 threads) per block
        k_scatter<<<blocks, 256>>>(ei, out);
    }
    // L3: normalize rows by 1/(sum(w)+eps)
    k_norm<<<(N_NODES * D / 4 + 255) / 256, 256>>>(out);
}

// round 16
// speedup vs baseline: 2.6522x; 1.0232x over previous
#include <cuda_runtime.h>
#include <cuda_fp16.h>
#include <math_constants.h>

#define N_NODES 100000
#define N_EDGES 1600000
#define D 64

// Scratch (allocation-free: __device__ globals)
__device__ float  g_w[N_NODES];              // exp(h . Wk) per node
__device__ float  g_sum[N_NODES];            // seg_sum of w over dst
__device__ __half g_hw[(size_t)N_NODES * D]; // fp16(w*h), INTERLEAVED layout:
                                             // row pos 2k   = dim k
                                             // row pos 2k+1 = dim k+32

// ---------------------------------------------------------------------------
// L0: warp per node. Softmax identity: score = aq[dst]+ak[src]+b and
// aq[dst]+b is constant within a dst group -> cancels exactly in softmax.
// Per-edge weight = w[src]/sum_dst(w), w = exp(h . Wk).
// Stores fp16(w*h) interleaved so scatter fetches dims (lane, lane+32) with
// ONE half2 gather (one dense 128B wavefront per edge).
// ---------------------------------------------------------------------------
__global__ void k_prep(const float* __restrict__ h,
                       const float* __restrict__ W,
                       float* __restrict__ out) {
    int node = (blockIdx.x * blockDim.x + threadIdx.x) >> 5;
    int lane = threadIdx.x & 31;
    if (node >= N_NODES) return;
    const float* hr = h + (size_t)node * D;
    float h0 = hr[lane], h1 = hr[lane + 32];
    float ak = h0 * W[D + lane] + h1 * W[D + lane + 32];
    #pragma unroll
    for (int off = 16; off > 0; off >>= 1)          // xor-reduce: all lanes get sum
        ak += __shfl_xor_sync(0xffffffffu, ak, off);
    float w = expf(ak);
    if (lane == 0) {
        g_w[node]   = w;
        g_sum[node] = 0.0f;
    }
    ((__half2*)(g_hw + (size_t)node * D))[lane] = __floats2half2_rn(w * h0, w * h1);
    out[(size_t)node * D + lane]      = 0.0f;
    out[(size_t)node * D + lane + 32] = 0.0f;
}

// ---------------------------------------------------------------------------
// L1: scatter (unnormalized) + fused w segment-sum. ONE warp = 8 edges x all
// 64 dims; lane covers dims (lane, lane+32) via a single half2 gather per
// edge. Lanes 0-7 additionally handle one edge each of the w-sum:
// gather w[src] + RED into g_sum (2 extra wavefronts per 8 edges; replaces
// the former standalone k_sum kernel).
// ---------------------------------------------------------------------------
__global__ void k_scatter(const int* __restrict__ ei,
                          float* __restrict__ out) {
    int gw   = (blockIdx.x * blockDim.x + threadIdx.x) >> 5;  // warp id
    int lane = threadIdx.x & 31;
    int e0   = gw << 3;                // 8 consecutive edges per warp
    if (e0 >= N_EDGES) return;

    int4 sa = ((const int4*)(ei + e0))[0];
    int4 sb = ((const int4*)(ei + e0))[1];
    int4 da = ((const int4*)(ei + N_EDGES + e0))[0];
    int4 db = ((const int4*)(ei + N_EDGES + e0))[1];
    int src[8] = {sa.x, sa.y, sa.z, sa.w, sb.x, sb.y, sb.z, sb.w};
    int dst[8] = {da.x, da.y, da.z, da.w, db.x, db.y, db.z, db.w};

    // fused w-sum: lanes 0-7, one edge each (scalar re-load avoids dynamic
    // register indexing; ei is L2-resident)
    float wsum = 0.0f;
    int   dsum = 0;
    if (lane < 8) {
        int s = __ldg(ei + e0 + lane);
        dsum  = __ldg(ei + N_EDGES + e0 + lane);
        wsum  = __ldg(g_w + s);
    }

    __half2 v[8];
    #pragma unroll
    for (int i = 0; i < 8; i++)
        v[i] = __ldg((const __half2*)(g_hw + (size_t)src[i] * D) + lane);

    if (lane < 8) atomicAdd(&g_sum[dsum], wsum);

    #pragma unroll
    for (int i = 0; i < 8; i++) {
        float2 f = __half22float2(v[i]);       // f.x = dim lane, f.y = dim lane+32
        float* p = out + (size_t)dst[i] * D + lane;
        atomicAdd(p,      f.x);
        atomicAdd(p + 32, f.y);
    }
}

// ---------------------------------------------------------------------------
// L2: normalize — out[n] *= 1/(sum[n]+eps). Each thread owns 4 independent
// float4 chunks of one node row (MLP 4; previous version was 1 chunk/thread
// at issue=16% -> latency-bound).
// ---------------------------------------------------------------------------
__global__ void k_norm(float* __restrict__ out) {
    int t = blockIdx.x * blockDim.x + threadIdx.x;
    if (t >= N_NODES * 4) return;          // 4 threads per node row
    int node = t >> 2;
    int j    = (t & 3) * 4;                // first of this thread's 4 float4s
    float ri = 1.0f / (__ldg(g_sum + node) + 1e-16f);
    float4* row = (float4*)(out + (size_t)node * D);
    float4 a = row[j], b = row[j + 1], c = row[j + 2], d = row[j + 3];
    a.x *= ri; a.y *= ri; a.z *= ri; a.w *= ri;
    b.x *= ri; b.y *= ri; b.z *= ri; b.w *= ri;
    c.x *= ri; c.y *= ri; c.z *= ri; c.w *= ri;
    d.x *= ri; d.y *= ri; d.z *= ri; d.w *= ri;
    row[j] = a; row[j + 1] = b; row[j + 2] = c; row[j + 3] = d;
}

// ---------------------------------------------------------------------------
extern "C" void kernel_launch(void* const* d_in, const int* in_sizes, int n_in,
                              void* d_out, int out_size) {
    const float* h   = (const float*)d_in[0];
    const float* W   = (const float*)d_in[2];
    const int*   ei  = (const int*)d_in[4];
    float*       out = (float*)d_out;

    // L0: node weights + interleaved hw=fp16(w*h) + zero out/sums
    k_prep<<<(N_NODES + 7) / 8, 256>>>(h, W, out);
    // L1: scatter + fused w-sum — warp covers 8 edges; warps = E/8 = 200000.
    {
        int warps  = N_EDGES / 8;
        int blocks = warps / 8;        // 8 warps (256 threads) per block
        k_scatter<<<blocks, 256>>>(ei, out);
    }
    // L2: normalize rows by 1/(sum(w)+eps), 4 threads per node
    k_norm<<<(N_NODES * 4 + 255) / 256, 256>>>(out);
}

// round 17
// speedup vs baseline: 2.7023x; 1.0189x over previous
#include <cuda_runtime.h>
#include <cuda_fp16.h>
#include <math_constants.h>

#define N_NODES 100000
#define N_EDGES 1600000
#define D 64

// Scratch (allocation-free: __device__ globals)
__device__ float  g_w[N_NODES];              // exp(h . Wk) per node
__device__ float  g_sum[N_NODES];            // seg_sum of w over dst
__device__ __half g_hw[(size_t)N_NODES * D]; // fp16(w*h), INTERLEAVED layout:
                                             // row pos 2k   = dim k
                                             // row pos 2k+1 = dim k+32

// ---------------------------------------------------------------------------
// L0: warp per 4 nodes (MLP 8). Softmax identity: score = aq[dst]+ak[src]+b
// and aq[dst]+b is constant within a dst group -> cancels exactly in the
// softmax. Per-edge weight = w[src]/sum_dst(w), w = exp(h . Wk).
// Stores fp16(w*h) interleaved so scatter fetches dims (lane, lane+32) with
// ONE half2 gather. Zeroing of out is 2 x ST.128 per 4 rows; g_w/g_sum are
// float4 stores (n0 is a multiple of 4 -> 16B aligned).
// ---------------------------------------------------------------------------
__global__ void k_prep(const float* __restrict__ h,
                       const float* __restrict__ W,
                       float* __restrict__ out) {
    int gw   = (blockIdx.x * blockDim.x + threadIdx.x) >> 5;
    int lane = threadIdx.x & 31;
    int n0   = gw << 2;                     // 4 nodes per warp; 100000 % 4 == 0
    if (n0 >= N_NODES) return;

    float wk0 = __ldg(W + D + lane);
    float wk1 = __ldg(W + D + lane + 32);

    const float* r0 = h + (size_t)n0 * D;
    float a0 = r0[lane],           b0 = r0[lane + 32];
    float a1 = r0[D + lane],       b1 = r0[D + lane + 32];
    float a2 = r0[2 * D + lane],   b2 = r0[2 * D + lane + 32];
    float a3 = r0[3 * D + lane],   b3 = r0[3 * D + lane + 32];

    float k0 = a0 * wk0 + b0 * wk1;
    float k1 = a1 * wk0 + b1 * wk1;
    float k2 = a2 * wk0 + b2 * wk1;
    float k3 = a3 * wk0 + b3 * wk1;
    #pragma unroll
    for (int off = 16; off > 0; off >>= 1) {   // 4 independent xor-reductions
        k0 += __shfl_xor_sync(0xffffffffu, k0, off);
        k1 += __shfl_xor_sync(0xffffffffu, k1, off);
        k2 += __shfl_xor_sync(0xffffffffu, k2, off);
        k3 += __shfl_xor_sync(0xffffffffu, k3, off);
    }
    float w0 = expf(k0), w1 = expf(k1), w2 = expf(k2), w3 = expf(k3);

    __half2* hw0 = (__half2*)(g_hw + (size_t)n0 * D);
    hw0[lane]          = __floats2half2_rn(w0 * a0, w0 * b0);
    hw0[32 + lane]     = __floats2half2_rn(w1 * a1, w1 * b1);
    hw0[64 + lane]     = __floats2half2_rn(w2 * a2, w2 * b2);
    hw0[96 + lane]     = __floats2half2_rn(w3 * a3, w3 * b3);

    float4 z = make_float4(0.f, 0.f, 0.f, 0.f);
    float4* o4 = (float4*)(out + (size_t)n0 * D);   // 4 rows = 64 float4
    o4[lane]      = z;
    o4[lane + 32] = z;

    if (lane == 0) {
        ((float4*)g_w)[gw]   = make_float4(w0, w1, w2, w3);
        ((float4*)g_sum)[gw] = z;
    }
}

// ---------------------------------------------------------------------------
// L1: scatter (unnormalized) + fused w segment-sum. ONE warp = 8 edges x all
// 64 dims; lane covers dims (lane, lane+32) via a single half2 gather per
// edge. Lanes 0-7 handle one edge each of the w-sum, selecting (src,dst)
// from the warp-uniform vector-load registers (ALU selects, no reloads).
// ---------------------------------------------------------------------------
__global__ void k_scatter(const int* __restrict__ ei,
                          float* __restrict__ out) {
    int gw   = (blockIdx.x * blockDim.x + threadIdx.x) >> 5;  // warp id
    int lane = threadIdx.x & 31;
    int e0   = gw << 3;                // 8 consecutive edges per warp
    if (e0 >= N_EDGES) return;

    int4 sa = ((const int4*)(ei + e0))[0];
    int4 sb = ((const int4*)(ei + e0))[1];
    int4 da = ((const int4*)(ei + N_EDGES + e0))[0];
    int4 db = ((const int4*)(ei + N_EDGES + e0))[1];
    int src[8] = {sa.x, sa.y, sa.z, sa.w, sb.x, sb.y, sb.z, sb.w};
    int dst[8] = {da.x, da.y, da.z, da.w, db.x, db.y, db.z, db.w};

    // fused w-sum: lanes 0-7, one edge each; indices come from the
    // warp-uniform registers via a select tree (no memory reloads).
    if (lane < 8) {
        int s, d;
        if (lane < 4) {
            s = (lane < 2) ? (lane == 0 ? sa.x : sa.y) : (lane == 2 ? sa.z : sa.w);
            d = (lane < 2) ? (lane == 0 ? da.x : da.y) : (lane == 2 ? da.z : da.w);
        } else {
            s = (lane < 6) ? (lane == 4 ? sb.x : sb.y) : (lane == 6 ? sb.z : sb.w);
            d = (lane < 6) ? (lane == 4 ? db.x : db.y) : (lane == 6 ? db.z : db.w);
        }
        atomicAdd(&g_sum[d], __ldg(g_w + s));
    }

    __half2 v[8];
    #pragma unroll
    for (int i = 0; i < 8; i++)
        v[i] = __ldg((const __half2*)(g_hw + (size_t)src[i] * D) + lane);

    #pragma unroll
    for (int i = 0; i < 8; i++) {
        float2 f = __half22float2(v[i]);       // f.x = dim lane, f.y = dim lane+32
        float* p = out + (size_t)dst[i] * D + lane;
        atomicAdd(p,      f.x);
        atomicAdd(p + 32, f.y);
    }
}

// ---------------------------------------------------------------------------
// L2: normalize — out[n] *= 1/(sum[n]+eps). Each thread owns 4 independent
// float4 chunks of one node row (MLP 4).
// ---------------------------------------------------------------------------
__global__ void k_norm(float* __restrict__ out) {
    int t = blockIdx.x * blockDim.x + threadIdx.x;
    if (t >= N_NODES * 4) return;          // 4 threads per node row
    int node = t >> 2;
    int j    = (t & 3) * 4;                // first of this thread's 4 float4s
    float ri = 1.0f / (__ldg(g_sum + node) + 1e-16f);
    float4* row = (float4*)(out + (size_t)node * D);
    float4 a = row[j], b = row[j + 1], c = row[j + 2], d = row[j + 3];
    a.x *= ri; a.y *= ri; a.z *= ri; a.w *= ri;
    b.x *= ri; b.y *= ri; b.z *= ri; b.w *= ri;
    c.x *= ri; c.y *= ri; c.z *= ri; c.w *= ri;
    d.x *= ri; d.y *= ri; d.z *= ri; d.w *= ri;
    row[j] = a; row[j + 1] = b; row[j + 2] = c; row[j + 3] = d;
}

// ---------------------------------------------------------------------------
extern "C" void kernel_launch(void* const* d_in, const int* in_sizes, int n_in,
                              void* d_out, int out_size) {
    const float* h   = (const float*)d_in[0];
    const float* W   = (const float*)d_in[2];
    const int*   ei  = (const int*)d_in[4];
    float*       out = (float*)d_out;

    // L0: node weights + interleaved hw=fp16(w*h) + zero out/sums.
    // 4 nodes per warp -> 25000 warps, 8 warps/block -> 3125 blocks.
    k_prep<<<(N_NODES / 4) / 8, 256>>>(h, W, out);
    // L1: scatter + fused w-sum — warp covers 8 edges; warps = E/8 = 200000.
    {
        int warps  = N_EDGES / 8;
        int blocks = warps / 8;        // 8 warps (256 threads) per block
        k_scatter<<<blocks, 256>>>(ei, out);
    }
    // L2: normalize rows by 1/(sum(w)+eps), 4 threads per node
    k_norm<<<(N_NODES * 4 + 255) / 256, 256>>>(out);
}